// round 1
// baseline (speedup 1.0000x reference)
#include <cuda_runtime.h>
#include <cuda_bf16.h>

// LocalVariation: x [16,1,512,512] f32 -> out [16,24,512,512] f32
// out[b, k(i,j), y, x] = x[b,y,x] - x[b, clamp(y+i-2), clamp(x+j-2)]
// for (i,j) in 5x5 window excluding center, replicate padding.
//
// HBM-store-bound: ~403 MB output write dominates. Each thread handles 4
// consecutive x-pixels (float4 stores), loading a 5x8 clamped window.

#define LV_H 512
#define LV_W 512
#define LV_B 16
#define LV_NCH 24

__global__ __launch_bounds__(256, 4)
void localvariation_kernel(const float* __restrict__ x, float* __restrict__ out)
{
    const int tx = threadIdx.x;            // 0..31
    const int ty = threadIdx.y;            // 0..7
    const int x0 = (blockIdx.x * 32 + tx) * 4;   // base x of 4-pixel group
    const int y  = blockIdx.y * 8 + ty;
    const int b  = blockIdx.z;

    const float* __restrict__ xb = x + (size_t)b * (LV_H * LV_W);

    // Load 5 rows x 8 cols window covering [x0-2, x0+5], rows [y-2, y+2],
    // replicate-clamped at borders.
    float w[5][8];
#pragma unroll
    for (int i = 0; i < 5; i++) {
        int yy = y + i - 2;
        yy = yy < 0 ? 0 : (yy > LV_H - 1 ? LV_H - 1 : yy);
        const float* __restrict__ row = xb + (size_t)yy * LV_W;
#pragma unroll
        for (int j = 0; j < 8; j++) {
            int xx = x0 + j - 2;
            xx = xx < 0 ? 0 : (xx > LV_W - 1 ? LV_W - 1 : xx);
            w[i][j] = __ldg(row + xx);
        }
    }

    // Center values for the 4 pixels.
    const float c0 = w[2][2], c1 = w[2][3], c2 = w[2][4], c3 = w[2][5];

    float* __restrict__ ob = out
        + (size_t)b * LV_NCH * (LV_H * LV_W)
        + (size_t)y * LV_W + x0;

    int k = 0;
#pragma unroll
    for (int i = 0; i < 5; i++) {
#pragma unroll
        for (int j = 0; j < 5; j++) {
            if (i == 2 && j == 2) continue;
            float4 v;
            v.x = c0 - w[i][j + 0];
            v.y = c1 - w[i][j + 1];
            v.z = c2 - w[i][j + 2];
            v.w = c3 - w[i][j + 3];
            *reinterpret_cast<float4*>(ob + (size_t)k * (LV_H * LV_W)) = v;
            k++;
        }
    }
}

extern "C" void kernel_launch(void* const* d_in, const int* in_sizes, int n_in,
                              void* d_out, int out_size)
{
    const float* x = (const float*)d_in[0];
    float* out = (float*)d_out;

    dim3 block(32, 8, 1);                       // 256 threads
    dim3 grid(LV_W / (32 * 4), LV_H / 8, LV_B); // (4, 64, 16) = 4096 blocks
    localvariation_kernel<<<grid, block>>>(x, out);
}

// round 2
// speedup vs baseline: 1.1464x; 1.1464x over previous
#include <cuda_runtime.h>
#include <cuda_bf16.h>

// LocalVariation: x [16,1,512,512] f32 -> out [16,24,512,512] f32
// out[b, k(i,j), y, x] = x[b,y,x] - x[b, clamp(y+i-2), clamp(x+j-2)]
// for (i,j) in 5x5 window excluding center, replicate padding.
//
// HBM-store-bound (~403 MB written once). Row-streamed: center row loaded as
// one float4, then each of the 5 window rows is loaded (8 clamped scalars,
// mostly L1/L2 hits) and its 4-5 output channels stored immediately via
// streaming stores (__stcs, evict-first) so the write-once output does not
// evict the 16.8 MB input from L2. Low register count -> high occupancy ->
// more stores in flight.

#define LV_H 512
#define LV_W 512
#define LV_B 16
#define LV_NCH 24
#define LV_HW (LV_H * LV_W)

__global__ __launch_bounds__(256)
void localvariation_kernel(const float* __restrict__ x, float* __restrict__ out)
{
    const int tx = threadIdx.x;            // 0..31
    const int ty = threadIdx.y;            // 0..7
    const int x0 = (blockIdx.x * 32 + tx) * 4;   // base x of 4-pixel group
    const int y  = blockIdx.y * 8 + ty;
    const int b  = blockIdx.z;

    const float* __restrict__ xb = x + (size_t)b * LV_HW;

    // Center values: aligned float4 at (y, x0) — never needs clamping.
    const float4 cc = *reinterpret_cast<const float4*>(xb + (size_t)y * LV_W + x0);
    const float c0 = cc.x, c1 = cc.y, c2 = cc.z, c3 = cc.w;

    float* __restrict__ ob = out
        + (size_t)b * LV_NCH * LV_HW
        + (size_t)y * LV_W + x0;

    int k = 0;
#pragma unroll
    for (int i = 0; i < 5; i++) {
        int yy = y + i - 2;
        yy = yy < 0 ? 0 : (yy > LV_H - 1 ? LV_H - 1 : yy);
        const float* __restrict__ row = xb + (size_t)yy * LV_W;

        // 8-wide clamped row segment [x0-2, x0+5].
        float r[8];
#pragma unroll
        for (int j = 0; j < 8; j++) {
            int xx = x0 + j - 2;
            xx = xx < 0 ? 0 : (xx > LV_W - 1 ? LV_W - 1 : xx);
            r[j] = __ldg(row + xx);
        }

        // Emit this row's channels immediately (streaming stores).
#pragma unroll
        for (int j = 0; j < 5; j++) {
            if (i == 2 && j == 2) continue;
            float4 v;
            v.x = c0 - r[j + 0];
            v.y = c1 - r[j + 1];
            v.z = c2 - r[j + 2];
            v.w = c3 - r[j + 3];
            __stcs(reinterpret_cast<float4*>(ob + (size_t)k * LV_HW), v);
            k++;
        }
    }
}

extern "C" void kernel_launch(void* const* d_in, const int* in_sizes, int n_in,
                              void* d_out, int out_size)
{
    const float* x = (const float*)d_in[0];
    float* out = (float*)d_out;

    dim3 block(32, 8, 1);                       // 256 threads
    dim3 grid(LV_W / (32 * 4), LV_H / 8, LV_B); // (4, 64, 16) = 4096 blocks
    localvariation_kernel<<<grid, block>>>(x, out);
}